// round 13
// baseline (speedup 1.0000x reference)
#include <cuda_runtime.h>
#include <math.h>

#define KP 4096
#define BP 8
#define THREADS 256          // 8 warps = 8 j-segments
#define WARPS 8
#define TILE_I 64            // i-points per block
#define IPT 2                // i-points per thread (lane l owns i = ibase + l + 32k)
#define TILE_J 1024          // j-points per smem tile
#define NTILE (KP / TILE_J)  // 4
#define WPAIRS (TILE_J / 2 / WARPS)  // 64 packed pairs per warp per tile
#define SMEM_FLOATS (4 * TILE_J)
#define SMEM_BYTES (SMEM_FLOATS * 4)   // 16 KB

#define W_CHAMFER 5.0f
#define W_KNN 3.0f
#define ALPHA 1.05f

__device__ float g_cham[BP * KP];
__device__ float g_value[BP * KP];
__device__ float g_batch[BP];

typedef unsigned long long u64;

__device__ __forceinline__ u64 pk2(float lo, float hi) {
    u64 r;
    asm("mov.b64 %0, {%1, %2};" : "=l"(r) : "f"(lo), "f"(hi));
    return r;
}
__device__ __forceinline__ void upk2(u64 v, float& lo, float& hi) {
    asm("mov.b64 {%0, %1}, %2;" : "=f"(lo), "=f"(hi) : "l"(v));
}
__device__ __forceinline__ u64 ffma2(u64 a, u64 b, u64 c) {
    u64 d;
    asm("fma.rn.f32x2 %0, %1, %2, %3;" : "=l"(d) : "l"(a), "l"(b), "l"(c));
    return d;
}

// Unconditional insert of d into ascending sorted 6-array (keeps 6 smallest).
// Safe no-op when d >= h[5].
__device__ __forceinline__ void insert6(float (&h)[6], float d) {
    h[5] = fminf(h[5], d);
#pragma unroll
    for (int m = 5; m >= 1; --m) {
        float lo = fminf(h[m - 1], h[m]);
        float hi = fmaxf(h[m - 1], h[m]);
        h[m - 1] = lo;
        h[m] = hi;
    }
}
// Guarded insert (merge paths / ultra-rare deep tail).
__device__ __forceinline__ void heap_insert(float (&h)[6], float d) {
    if (d < h[5]) insert6(h, d);
}

#define CSWAP(a, b)                         \
    {                                       \
        float _lo = fminf(a, b);            \
        float _hi = fmaxf(a, b);            \
        a = _lo;                            \
        b = _hi;                            \
    }

__global__ void __launch_bounds__(THREADS)
dist_kernel(const float* __restrict__ adv, const float* __restrict__ ori) {
    extern __shared__ float sm[];
    float* s_x = sm;
    float* s_y = sm + TILE_J;
    float* s_z = sm + 2 * TILE_J;
    float* s_s = sm + 3 * TILE_J;
    const u64* s_x2 = (const u64*)s_x;   // direct LDS.64 into packed pairs
    const u64* s_y2 = (const u64*)s_y;
    const u64* s_z2 = (const u64*)s_z;
    const u64* s_s2 = (const u64*)s_s;

    const int b   = blockIdx.y;
    const int tid = threadIdx.x;
    const int seg = tid >> 5;        // warp id = j-segment (0..7)
    const int l   = tid & 31;        // lane
    const int ibase = blockIdx.x * TILE_I;
    const float* A = adv + (size_t)b * KP * 3;
    const float* O = ori + (size_t)b * KP * 3;
    const unsigned full = 0xffffffffu;

    // Per-thread i-points: i = ibase + l + 32*k
    u64 mx2[IPT], my2[IPT], mz2[IPT];
    float ci[IPT], cl[IPT], ch[IPT];
    float h[IPT][6];
#pragma unroll
    for (int k = 0; k < IPT; ++k) {
        int i = ibase + l + 32 * k;
        float x = A[3 * i + 0], y = A[3 * i + 1], z = A[3 * i + 2];
        float mx = -2.0f * x, my = -2.0f * y, mz = -2.0f * z;
        mx2[k] = pk2(mx, mx);
        my2[k] = pk2(my, my);
        mz2[k] = pk2(mz, mz);
        ci[k] = fmaf(x, x, fmaf(y, y, z * z));
        cl[k] = 3.4e38f; ch[k] = 3.4e38f;
#pragma unroll
        for (int m = 0; m < 6; ++m) h[k][m] = 3.4e38f;
    }

    // ---- Phase 1: Chamfer (min over ori). Distances EXCLUDE +ci (added at end). ----
    for (int t = 0; t < NTILE; ++t) {
        __syncthreads();
        const float* P = O + (size_t)(t * TILE_J) * 3;
        for (int j = tid; j < TILE_J; j += THREADS) {
            float x = P[3 * j + 0], y = P[3 * j + 1], z = P[3 * j + 2];
            s_x[j] = x; s_y[j] = y; s_z[j] = z;
            s_s[j] = fmaf(x, x, fmaf(y, y, z * z));
        }
        __syncthreads();

        const int pbeg = seg * WPAIRS;
#pragma unroll 8
        for (int p = pbeg; p < pbeg + WPAIRS; ++p) {
            u64 xj = s_x2[p], yj = s_y2[p], zj = s_z2[p], sj = s_s2[p];
#pragma unroll
            for (int k = 0; k < IPT; ++k) {
                u64 d = ffma2(mz2[k], zj, ffma2(my2[k], yj, ffma2(mx2[k], xj, sj)));
                float dl, dh;
                upk2(d, dl, dh);
                cl[k] = fminf(cl[k], dl);
                ch[k] = fminf(ch[k], dh);
            }
        }
    }

    // ---- Phase 2: kNN — 6 smallest within adv (self included; ci-offset dropped) ----
    // Groups of 4 packed pairs (8 distances): full sort8 (19 comparators),
    // ONE unconditional insert of the group min, nested rare branches after.
    for (int t = 0; t < NTILE; ++t) {
        __syncthreads();
        const float* P = A + (size_t)(t * TILE_J) * 3;
        for (int j = tid; j < TILE_J; j += THREADS) {
            float x = P[3 * j + 0], y = P[3 * j + 1], z = P[3 * j + 2];
            s_x[j] = x; s_y[j] = y; s_z[j] = z;
            s_s[j] = fmaf(x, x, fmaf(y, y, z * z));
        }
        __syncthreads();

        const int pbeg = seg * WPAIRS;
#pragma unroll 1
        for (int p = pbeg; p < pbeg + WPAIRS; p += 4) {
            u64 xa = s_x2[p],     ya = s_y2[p],     za = s_z2[p],     sa = s_s2[p];
            u64 xb = s_x2[p + 1], yb = s_y2[p + 1], zb = s_z2[p + 1], sb = s_s2[p + 1];
            u64 xc = s_x2[p + 2], yc = s_y2[p + 2], zc = s_z2[p + 2], sc = s_s2[p + 2];
            u64 xd = s_x2[p + 3], yd = s_y2[p + 3], zd = s_z2[p + 3], sd = s_s2[p + 3];
#pragma unroll
            for (int k = 0; k < IPT; ++k) {
                u64 da = ffma2(mz2[k], za, ffma2(my2[k], ya, ffma2(mx2[k], xa, sa)));
                u64 db = ffma2(mz2[k], zb, ffma2(my2[k], yb, ffma2(mx2[k], xb, sb)));
                u64 dc = ffma2(mz2[k], zc, ffma2(my2[k], yc, ffma2(mx2[k], xc, sc)));
                u64 dd = ffma2(mz2[k], zd, ffma2(my2[k], yd, ffma2(mx2[k], xd, sd)));
                float s0, s1, s2, s3, s4, s5, s6, s7;
                upk2(da, s0, s1);
                upk2(db, s2, s3);
                upk2(dc, s4, s5);
                upk2(dd, s6, s7);
                // 19-comparator sort8 (ascending)
                CSWAP(s0, s1); CSWAP(s2, s3); CSWAP(s4, s5); CSWAP(s6, s7);
                CSWAP(s0, s2); CSWAP(s1, s3); CSWAP(s4, s6); CSWAP(s5, s7);
                CSWAP(s1, s2); CSWAP(s5, s6); CSWAP(s0, s4); CSWAP(s3, s7);
                CSWAP(s1, s5); CSWAP(s2, s6);
                CSWAP(s1, s4); CSWAP(s3, s6);
                CSWAP(s2, s4); CSWAP(s3, s5);
                CSWAP(s3, s4);
                // Branchless hot path: group min (no-op if not qualifying)
                insert6(h[k], s0);
                // s1 qualifies rarely; deeper levels vanishingly rare.
                bool c1 = s1 < h[k][5];
                if (__any_sync(full, c1)) {
                    if (c1) insert6(h[k], s1);
                    bool c2 = s2 < h[k][5];
                    if (__any_sync(full, c2)) {
                        if (c2) insert6(h[k], s2);
                        bool c3 = s3 < h[k][5];
                        if (__any_sync(full, c3)) {
                            if (c3) insert6(h[k], s3);
                            // ~never: guarded tail (exact; no-ops when >= h[5])
                            heap_insert(h[k], s4);
                            heap_insert(h[k], s5);
                            heap_insert(h[k], s6);
                            heap_insert(h[k], s7);
                        }
                    }
                }
            }
        }
    }

    // Fold packed chamfer halves
    float cmin[IPT];
#pragma unroll
    for (int k = 0; k < IPT; ++k) cmin[k] = fminf(cl[k], ch[k]);

    // ---- Cross-warp merge (3-round tree), reusing tile smem as buffer ----
    float* buf = sm;

#define MERGE_WRITE(SLOT)                                                   \
    {                                                                       \
        float* w = buf + (((size_t)(SLOT) * 32 + l) * IPT) * 7;             \
        _Pragma("unroll")                                                   \
        for (int k = 0; k < IPT; ++k) {                                     \
            w[k * 7 + 0] = cmin[k];                                         \
            _Pragma("unroll")                                               \
            for (int m = 0; m < 6; ++m) w[k * 7 + 1 + m] = h[k][m];         \
        }                                                                   \
    }
#define MERGE_READ(SLOT)                                                    \
    {                                                                       \
        const float* r = buf + (((size_t)(SLOT) * 32 + l) * IPT) * 7;       \
        _Pragma("unroll")                                                   \
        for (int k = 0; k < IPT; ++k) {                                     \
            cmin[k] = fminf(cmin[k], r[k * 7 + 0]);                         \
            _Pragma("unroll")                                               \
            for (int m = 0; m < 6; ++m) heap_insert(h[k], r[k * 7 + 1 + m]);\
        }                                                                   \
    }

    __syncthreads();
    if (seg >= 4) MERGE_WRITE(seg - 4);
    __syncthreads();
    if (seg < 4) MERGE_READ(seg);
    __syncthreads();
    if (seg == 2 || seg == 3) MERGE_WRITE(seg - 2);
    __syncthreads();
    if (seg < 2) MERGE_READ(seg);
    __syncthreads();
    if (seg == 1) MERGE_WRITE(0);
    __syncthreads();
    if (seg == 0) {
        MERGE_READ(0);
#pragma unroll
        for (int k = 0; k < IPT; ++k) {
            int i = ibase + l + 32 * k;
            g_cham[b * KP + i] = cmin[k] + ci[k];
            // drop h[0] (self), mean of next 5, re-add ci offset
            g_value[b * KP + i] =
                fmaf(0.2f, h[k][1] + h[k][2] + h[k][3] + h[k][4] + h[k][5], ci[k]);
        }
    }
}

// Warp-shuffle block reduction (256 thr): result valid in thread 0.
__device__ __forceinline__ float block_sum(float v, float* red) {
    const unsigned full = 0xffffffffu;
#pragma unroll
    for (int o = 16; o > 0; o >>= 1) v += __shfl_xor_sync(full, v, o);
    const int w = threadIdx.x >> 5;
    if ((threadIdx.x & 31) == 0) red[w] = v;
    __syncthreads();
    float r = 0.0f;
    if (threadIdx.x < 8) r = red[threadIdx.x];
#pragma unroll
    for (int o = 4; o > 0; o >>= 1) r += __shfl_xor_sync(full, r, o);
    __syncthreads();
    return r;   // thread 0 holds the sum
}

__global__ void __launch_bounds__(256)
reduce_kernel() {
    __shared__ float red[8];
    __shared__ float s_bcast[2];
    const int b = blockIdx.x;
    const int tid = threadIdx.x;
    const float* cham = g_cham + b * KP;
    const float* val  = g_value + b * KP;

    float s1 = 0.0f, s2 = 0.0f;
    for (int i = tid; i < KP; i += 256) { s1 += cham[i]; s2 += val[i]; }
    float cham_sum = block_sum(s1, red);
    float val_sum  = block_sum(s2, red);
    if (tid == 0) s_bcast[0] = val_sum * (1.0f / KP);
    __syncthreads();
    float mean = s_bcast[0];

    float s3 = 0.0f;
    for (int i = tid; i < KP; i += 256) {
        float d = val[i] - mean;
        s3 = fmaf(d, d, s3);
    }
    float var_sum = block_sum(s3, red);
    if (tid == 0) {
        float stdv = sqrtf(var_sum * (1.0f / (KP - 1)));   // ddof=1
        s_bcast[1] = fmaf(ALPHA, stdv, mean);
    }
    __syncthreads();
    float thr = s_bcast[1];

    float s4 = 0.0f;
    for (int i = tid; i < KP; i += 256) {
        float v = val[i];
        if (v > thr) s4 += v;
    }
    float msum = block_sum(s4, red);

    if (tid == 0) {
        float cham_mean = cham_sum * (1.0f / KP);
        float knn_mean  = msum * (1.0f / KP);
        g_batch[b] = cham_mean * W_CHAMFER + knn_mean * W_KNN;
    }
}

__global__ void final_kernel(float* __restrict__ out) {
    if (threadIdx.x == 0) {
        float s = 0.0f;
#pragma unroll
        for (int b = 0; b < BP; ++b) s += g_batch[b];
        out[0] = s * (1.0f / BP);
    }
}

extern "C" void kernel_launch(void* const* d_in, const int* in_sizes, int n_in,
                              void* d_out, int out_size) {
    const float* adv = (const float*)d_in[0];
    const float* ori = (const float*)d_in[1];
    float* out = (float*)d_out;

    dist_kernel<<<dim3(KP / TILE_I, BP), THREADS, SMEM_BYTES>>>(adv, ori);
    reduce_kernel<<<BP, 256>>>();
    final_kernel<<<1, 32>>>(out);
}

// round 16
// speedup vs baseline: 1.0587x; 1.0587x over previous
#include <cuda_runtime.h>
#include <math.h>

#define KP 4096
#define BP 8
#define THREADS 256          // 8 warps = 8 j-segments
#define WARPS 8
#define TILE_I 64            // i-points per block
#define IPT 2                // i-points per thread (lane l owns i = ibase + l + 32k)
#define TILE_J 1024          // j-points per smem tile
#define NTILE (KP / TILE_J)  // 4
#define WPAIRS (TILE_J / 2 / WARPS)  // 64 packed pairs per warp per tile
#define SMEM_FLOATS (4 * TILE_J)
#define SMEM_BYTES (SMEM_FLOATS * 4)   // 16 KB

#define W_CHAMFER 5.0f
#define W_KNN 3.0f
#define ALPHA 1.05f

__device__ float g_cham[BP * KP];
__device__ float g_value[BP * KP];
__device__ float g_batch[BP];

typedef unsigned long long u64;

__device__ __forceinline__ u64 pk2(float lo, float hi) {
    u64 r;
    asm("mov.b64 %0, {%1, %2};" : "=l"(r) : "f"(lo), "f"(hi));
    return r;
}
__device__ __forceinline__ void upk2(u64 v, float& lo, float& hi) {
    asm("mov.b64 {%0, %1}, %2;" : "=f"(lo), "=f"(hi) : "l"(v));
}
__device__ __forceinline__ u64 ffma2(u64 a, u64 b, u64 c) {
    u64 d;
    asm("fma.rn.f32x2 %0, %1, %2, %3;" : "=l"(d) : "l"(a), "l"(b), "l"(c));
    return d;
}

// Unconditional insert of d into ascending sorted 6-array (keeps 6 smallest).
// Safe no-op when d >= h[5].
__device__ __forceinline__ void insert6(float (&h)[6], float d) {
    h[5] = fminf(h[5], d);
#pragma unroll
    for (int m = 5; m >= 1; --m) {
        float lo = fminf(h[m - 1], h[m]);
        float hi = fmaxf(h[m - 1], h[m]);
        h[m - 1] = lo;
        h[m] = hi;
    }
}
// Guarded insert (merge paths / rare branches).
__device__ __forceinline__ void heap_insert(float (&h)[6], float d) {
    if (d < h[5]) insert6(h, d);
}

__global__ void __launch_bounds__(THREADS)
dist_kernel(const float* __restrict__ adv, const float* __restrict__ ori) {
    extern __shared__ float sm[];
    float* s_x = sm;
    float* s_y = sm + TILE_J;
    float* s_z = sm + 2 * TILE_J;
    float* s_s = sm + 3 * TILE_J;
    const u64* s_x2 = (const u64*)s_x;   // direct LDS.64 into packed pairs
    const u64* s_y2 = (const u64*)s_y;
    const u64* s_z2 = (const u64*)s_z;
    const u64* s_s2 = (const u64*)s_s;

    const int b   = blockIdx.y;
    const int tid = threadIdx.x;
    const int seg = tid >> 5;        // warp id = j-segment (0..7)
    const int l   = tid & 31;        // lane
    const int ibase = blockIdx.x * TILE_I;
    const float* A = adv + (size_t)b * KP * 3;
    const float* O = ori + (size_t)b * KP * 3;
    const unsigned full = 0xffffffffu;

    // Per-thread i-points: i = ibase + l + 32*k
    u64 mx2[IPT], my2[IPT], mz2[IPT];
    float ci[IPT], cl[IPT], ch[IPT];
    float h[IPT][6];
#pragma unroll
    for (int k = 0; k < IPT; ++k) {
        int i = ibase + l + 32 * k;
        float x = A[3 * i + 0], y = A[3 * i + 1], z = A[3 * i + 2];
        float mx = -2.0f * x, my = -2.0f * y, mz = -2.0f * z;
        mx2[k] = pk2(mx, mx);
        my2[k] = pk2(my, my);
        mz2[k] = pk2(mz, mz);
        ci[k] = fmaf(x, x, fmaf(y, y, z * z));
        cl[k] = 3.4e38f; ch[k] = 3.4e38f;
#pragma unroll
        for (int m = 0; m < 6; ++m) h[k][m] = 3.4e38f;
    }

    // ---- Phase 1: Chamfer (min over ori). Distances EXCLUDE +ci (added at end). ----
    for (int t = 0; t < NTILE; ++t) {
        __syncthreads();
        const float* P = O + (size_t)(t * TILE_J) * 3;
        for (int j = tid; j < TILE_J; j += THREADS) {
            float x = P[3 * j + 0], y = P[3 * j + 1], z = P[3 * j + 2];
            s_x[j] = x; s_y[j] = y; s_z[j] = z;
            s_s[j] = fmaf(x, x, fmaf(y, y, z * z));
        }
        __syncthreads();

        const int pbeg = seg * WPAIRS;
#pragma unroll 8
        for (int p = pbeg; p < pbeg + WPAIRS; ++p) {
            u64 xj = s_x2[p], yj = s_y2[p], zj = s_z2[p], sj = s_s2[p];
#pragma unroll
            for (int k = 0; k < IPT; ++k) {
                u64 d = ffma2(mz2[k], zj, ffma2(my2[k], yj, ffma2(mx2[k], xj, sj)));
                float dl, dh;
                upk2(d, dl, dh);
                cl[k] = fminf(cl[k], dl);
                ch[k] = fminf(ch[k], dh);
            }
        }
    }

    // ---- Phase 2: kNN — 6 smallest within adv (self included; ci-offset dropped) ----
    // Groups of 4 packed pairs (8 distances) = two sort4-lite halves.
    // Common path: min+2nd per half (8 FMNMX each), ONE insert6 of the group
    // min. Deep values (3rd/4th of each half) reconstructed lazily in the
    // rare branch. Exact: per-half sortedness makes each gate a true lower
    // bound on all remaining values; all rare-path inserts are guarded; all
    // 8 values are distinct distances (no duplicate-insert hazard).
    for (int t = 0; t < NTILE; ++t) {
        __syncthreads();
        const float* P = A + (size_t)(t * TILE_J) * 3;
        for (int j = tid; j < TILE_J; j += THREADS) {
            float x = P[3 * j + 0], y = P[3 * j + 1], z = P[3 * j + 2];
            s_x[j] = x; s_y[j] = y; s_z[j] = z;
            s_s[j] = fmaf(x, x, fmaf(y, y, z * z));
        }
        __syncthreads();

        const int pbeg = seg * WPAIRS;
#pragma unroll 2
        for (int p = pbeg; p < pbeg + WPAIRS; p += 4) {
            u64 xa = s_x2[p],     ya = s_y2[p],     za = s_z2[p],     sa = s_s2[p];
            u64 xb = s_x2[p + 1], yb = s_y2[p + 1], zb = s_z2[p + 1], sb = s_s2[p + 1];
            u64 xc = s_x2[p + 2], yc = s_y2[p + 2], zc = s_z2[p + 2], sc = s_s2[p + 2];
            u64 xd = s_x2[p + 3], yd = s_y2[p + 3], zd = s_z2[p + 3], sd = s_s2[p + 3];
#pragma unroll
            for (int k = 0; k < IPT; ++k) {
                u64 da = ffma2(mz2[k], za, ffma2(my2[k], ya, ffma2(mx2[k], xa, sa)));
                u64 db = ffma2(mz2[k], zb, ffma2(my2[k], yb, ffma2(mx2[k], xb, sb)));
                u64 dc = ffma2(mz2[k], zc, ffma2(my2[k], yc, ffma2(mx2[k], xc, sc)));
                u64 dd = ffma2(mz2[k], zd, ffma2(my2[k], yd, ffma2(mx2[k], xd, sd)));
                float v0, v1, v2, v3, v4, v5, v6, v7;
                upk2(da, v0, v1);
                upk2(db, v2, v3);
                upk2(dc, v4, v5);
                upk2(dd, v6, v7);
                // half A (v0..v3): min + 2nd, save temps for lazy deep
                float t1a = fminf(v0, v1), t2a = fmaxf(v0, v1);
                float t3a = fminf(v2, v3), t4a = fmaxf(v2, v3);
                float s0a = fminf(t1a, t3a), m1a = fmaxf(t1a, t3a);
                float m2a = fminf(t2a, t4a);
                float s1a = fminf(m1a, m2a);
                // half B (v4..v7)
                float t1b = fminf(v4, v5), t2b = fmaxf(v4, v5);
                float t3b = fminf(v6, v7), t4b = fmaxf(v6, v7);
                float s0b = fminf(t1b, t3b), m1b = fmaxf(t1b, t3b);
                float m2b = fminf(t2b, t4b);
                float s1b = fminf(m1b, m2b);
                // group min: unconditional insert (no-op if not qualifying)
                float g0 = fminf(s0a, s0b);
                insert6(h[k], g0);
                // exact lower bound on ALL remaining 7 values of the group
                float loser = fmaxf(s0a, s0b);
                float cand = fminf(loser, fminf(s1a, s1b));
                bool c1 = cand < h[k][5];
                if (__any_sync(full, c1)) {
                    if (c1) {
                        heap_insert(h[k], loser);
                        heap_insert(h[k], s1a);
                        heap_insert(h[k], s1b);
                    }
                    // lazy deep values; gate is exact lower bound on them
                    float s2a = fmaxf(m1a, m2a), s2b = fmaxf(m1b, m2b);
                    bool c2 = fminf(s2a, s2b) < h[k][5];
                    if (__any_sync(full, c2)) {
                        if (c2) {
                            heap_insert(h[k], s2a);
                            heap_insert(h[k], s2b);
                            heap_insert(h[k], fmaxf(t2a, t4a));   // s3a
                            heap_insert(h[k], fmaxf(t2b, t4b));   // s3b
                        }
                    }
                }
            }
        }
    }

    // Fold packed chamfer halves
    float cmin[IPT];
#pragma unroll
    for (int k = 0; k < IPT; ++k) cmin[k] = fminf(cl[k], ch[k]);

    // ---- Cross-warp merge (3-round tree), reusing tile smem as buffer ----
    float* buf = sm;

#define MERGE_WRITE(SLOT)                                                   \
    {                                                                       \
        float* w = buf + (((size_t)(SLOT) * 32 + l) * IPT) * 7;             \
        _Pragma("unroll")                                                   \
        for (int k = 0; k < IPT; ++k) {                                     \
            w[k * 7 + 0] = cmin[k];                                         \
            _Pragma("unroll")                                               \
            for (int m = 0; m < 6; ++m) w[k * 7 + 1 + m] = h[k][m];         \
        }                                                                   \
    }
#define MERGE_READ(SLOT)                                                    \
    {                                                                       \
        const float* r = buf + (((size_t)(SLOT) * 32 + l) * IPT) * 7;       \
        _Pragma("unroll")                                                   \
        for (int k = 0; k < IPT; ++k) {                                     \
            cmin[k] = fminf(cmin[k], r[k * 7 + 0]);                         \
            _Pragma("unroll")                                               \
            for (int m = 0; m < 6; ++m) heap_insert(h[k], r[k * 7 + 1 + m]);\
        }                                                                   \
    }

    __syncthreads();
    if (seg >= 4) MERGE_WRITE(seg - 4);
    __syncthreads();
    if (seg < 4) MERGE_READ(seg);
    __syncthreads();
    if (seg == 2 || seg == 3) MERGE_WRITE(seg - 2);
    __syncthreads();
    if (seg < 2) MERGE_READ(seg);
    __syncthreads();
    if (seg == 1) MERGE_WRITE(0);
    __syncthreads();
    if (seg == 0) {
        MERGE_READ(0);
#pragma unroll
        for (int k = 0; k < IPT; ++k) {
            int i = ibase + l + 32 * k;
            g_cham[b * KP + i] = cmin[k] + ci[k];
            // drop h[0] (self), mean of next 5, re-add ci offset
            g_value[b * KP + i] =
                fmaf(0.2f, h[k][1] + h[k][2] + h[k][3] + h[k][4] + h[k][5], ci[k]);
        }
    }
}

// Warp-shuffle block reduction (256 thr): result valid in thread 0.
__device__ __forceinline__ float block_sum(float v, float* red) {
    const unsigned full = 0xffffffffu;
#pragma unroll
    for (int o = 16; o > 0; o >>= 1) v += __shfl_xor_sync(full, v, o);
    const int w = threadIdx.x >> 5;
    if ((threadIdx.x & 31) == 0) red[w] = v;
    __syncthreads();
    float r = 0.0f;
    if (threadIdx.x < 8) r = red[threadIdx.x];
#pragma unroll
    for (int o = 4; o > 0; o >>= 1) r += __shfl_xor_sync(full, r, o);
    __syncthreads();
    return r;   // thread 0 holds the sum
}

__global__ void __launch_bounds__(256)
reduce_kernel() {
    __shared__ float red[8];
    __shared__ float s_bcast[2];
    const int b = blockIdx.x;
    const int tid = threadIdx.x;
    const float* cham = g_cham + b * KP;
    const float* val  = g_value + b * KP;

    float s1 = 0.0f, s2 = 0.0f;
    for (int i = tid; i < KP; i += 256) { s1 += cham[i]; s2 += val[i]; }
    float cham_sum = block_sum(s1, red);
    float val_sum  = block_sum(s2, red);
    if (tid == 0) s_bcast[0] = val_sum * (1.0f / KP);
    __syncthreads();
    float mean = s_bcast[0];

    float s3 = 0.0f;
    for (int i = tid; i < KP; i += 256) {
        float d = val[i] - mean;
        s3 = fmaf(d, d, s3);
    }
    float var_sum = block_sum(s3, red);
    if (tid == 0) {
        float stdv = sqrtf(var_sum * (1.0f / (KP - 1)));   // ddof=1
        s_bcast[1] = fmaf(ALPHA, stdv, mean);
    }
    __syncthreads();
    float thr = s_bcast[1];

    float s4 = 0.0f;
    for (int i = tid; i < KP; i += 256) {
        float v = val[i];
        if (v > thr) s4 += v;
    }
    float msum = block_sum(s4, red);

    if (tid == 0) {
        float cham_mean = cham_sum * (1.0f / KP);
        float knn_mean  = msum * (1.0f / KP);
        g_batch[b] = cham_mean * W_CHAMFER + knn_mean * W_KNN;
    }
}

__global__ void final_kernel(float* __restrict__ out) {
    if (threadIdx.x == 0) {
        float s = 0.0f;
#pragma unroll
        for (int b = 0; b < BP; ++b) s += g_batch[b];
        out[0] = s * (1.0f / BP);
    }
}

extern "C" void kernel_launch(void* const* d_in, const int* in_sizes, int n_in,
                              void* d_out, int out_size) {
    const float* adv = (const float*)d_in[0];
    const float* ori = (const float*)d_in[1];
    float* out = (float*)d_out;

    dist_kernel<<<dim3(KP / TILE_I, BP), THREADS, SMEM_BYTES>>>(adv, ori);
    reduce_kernel<<<BP, 256>>>();
    final_kernel<<<1, 32>>>(out);
}

// round 17
// speedup vs baseline: 1.1169x; 1.0550x over previous
#include <cuda_runtime.h>
#include <math.h>

#define KP 4096
#define BP 8
#define THREADS 256          // 8 warps = 8 j-segments
#define WARPS 8
#define TILE_I 64            // i-points per block
#define IPT 2                // i-points per thread (lane l owns i = ibase + l + 32k)
#define TILE_J 1024          // j-points per smem tile
#define NTILE (KP / TILE_J)  // 4
#define WPAIRS (TILE_J / 2 / WARPS)  // 64 packed pairs per warp per tile
#define SMEM_FLOATS (4 * TILE_J)
#define SMEM_BYTES (SMEM_FLOATS * 4)   // 16 KB

#define W_CHAMFER 5.0f
#define W_KNN 3.0f
#define ALPHA 1.05f

__device__ float g_cham[BP * KP];
__device__ float g_value[BP * KP];
__device__ float g_batch[BP];

typedef unsigned long long u64;

__device__ __forceinline__ u64 pk2(float lo, float hi) {
    u64 r;
    asm("mov.b64 %0, {%1, %2};" : "=l"(r) : "f"(lo), "f"(hi));
    return r;
}
__device__ __forceinline__ void upk2(u64 v, float& lo, float& hi) {
    asm("mov.b64 {%0, %1}, %2;" : "=f"(lo), "=f"(hi) : "l"(v));
}
__device__ __forceinline__ u64 ffma2(u64 a, u64 b, u64 c) {
    u64 d;
    asm("fma.rn.f32x2 %0, %1, %2, %3;" : "=l"(d) : "l"(a), "l"(b), "l"(c));
    return d;
}

// Unconditional insert of d into ascending sorted 6-array (keeps 6 smallest).
// Safe no-op when d >= h[5].
__device__ __forceinline__ void insert6(float (&h)[6], float d) {
    h[5] = fminf(h[5], d);
#pragma unroll
    for (int m = 5; m >= 1; --m) {
        float lo = fminf(h[m - 1], h[m]);
        float hi = fmaxf(h[m - 1], h[m]);
        h[m - 1] = lo;
        h[m] = hi;
    }
}
// Guarded insert (merge paths / rare branches).
__device__ __forceinline__ void heap_insert(float (&h)[6], float d) {
    if (d < h[5]) insert6(h, d);
}

__global__ void __launch_bounds__(THREADS, 4)
dist_kernel(const float* __restrict__ adv, const float* __restrict__ ori) {
    extern __shared__ float sm[];
    float* s_x = sm;
    float* s_y = sm + TILE_J;
    float* s_z = sm + 2 * TILE_J;
    float* s_s = sm + 3 * TILE_J;
    const u64* s_x2 = (const u64*)s_x;   // direct LDS.64 into packed pairs
    const u64* s_y2 = (const u64*)s_y;
    const u64* s_z2 = (const u64*)s_z;
    const u64* s_s2 = (const u64*)s_s;

    const int b   = blockIdx.y;
    const int tid = threadIdx.x;
    const int seg = tid >> 5;        // warp id = j-segment (0..7)
    const int l   = tid & 31;        // lane
    const int ibase = blockIdx.x * TILE_I;
    const float* A = adv + (size_t)b * KP * 3;
    const float* O = ori + (size_t)b * KP * 3;
    const unsigned full = 0xffffffffu;

    // Per-thread i-points: i = ibase + l + 32*k
    u64 mx2[IPT], my2[IPT], mz2[IPT];
    float ci[IPT], cl[IPT], ch[IPT];
    float h[IPT][6];
#pragma unroll
    for (int k = 0; k < IPT; ++k) {
        int i = ibase + l + 32 * k;
        float x = A[3 * i + 0], y = A[3 * i + 1], z = A[3 * i + 2];
        float mx = -2.0f * x, my = -2.0f * y, mz = -2.0f * z;
        mx2[k] = pk2(mx, mx);
        my2[k] = pk2(my, my);
        mz2[k] = pk2(mz, mz);
        ci[k] = fmaf(x, x, fmaf(y, y, z * z));
        cl[k] = 3.4e38f; ch[k] = 3.4e38f;
#pragma unroll
        for (int m = 0; m < 6; ++m) h[k][m] = 3.4e38f;
    }

    // ---- Phase 1: Chamfer (min over ori). Distances EXCLUDE +ci (added at end). ----
    for (int t = 0; t < NTILE; ++t) {
        __syncthreads();
        const float* P = O + (size_t)(t * TILE_J) * 3;
        for (int j = tid; j < TILE_J; j += THREADS) {
            float x = P[3 * j + 0], y = P[3 * j + 1], z = P[3 * j + 2];
            s_x[j] = x; s_y[j] = y; s_z[j] = z;
            s_s[j] = fmaf(x, x, fmaf(y, y, z * z));
        }
        __syncthreads();

        const int pbeg = seg * WPAIRS;
#pragma unroll 8
        for (int p = pbeg; p < pbeg + WPAIRS; ++p) {
            u64 xj = s_x2[p], yj = s_y2[p], zj = s_z2[p], sj = s_s2[p];
#pragma unroll
            for (int k = 0; k < IPT; ++k) {
                u64 d = ffma2(mz2[k], zj, ffma2(my2[k], yj, ffma2(mx2[k], xj, sj)));
                float dl, dh;
                upk2(d, dl, dh);
                cl[k] = fminf(cl[k], dl);
                ch[k] = fminf(ch[k], dh);
            }
        }
    }

    // ---- Phase 2: kNN — 6 smallest within adv (self included; ci-offset dropped) ----
    // Groups of 4 packed pairs (8 distances) = two sort4-lite halves,
    // loaded SEQUENTIALLY (halves the peak load-register liveness so the
    // 64-reg budget schedules without hot-path spills).
    // Common path: min+2nd per half, ONE insert6 of the group min. Deep
    // values reconstructed lazily in the rare branch. Exact: per-half
    // sortedness makes each gate a true lower bound; all rare-path inserts
    // guarded; 8 distinct distances (no duplicate-insert hazard).
    for (int t = 0; t < NTILE; ++t) {
        __syncthreads();
        const float* P = A + (size_t)(t * TILE_J) * 3;
        for (int j = tid; j < TILE_J; j += THREADS) {
            float x = P[3 * j + 0], y = P[3 * j + 1], z = P[3 * j + 2];
            s_x[j] = x; s_y[j] = y; s_z[j] = z;
            s_s[j] = fmaf(x, x, fmaf(y, y, z * z));
        }
        __syncthreads();

        const int pbeg = seg * WPAIRS;
#pragma unroll 2
        for (int p = pbeg; p < pbeg + WPAIRS; p += 4) {
            // half A distances (pairs p, p+1)
            u64 da[IPT], db[IPT];
            {
                u64 xa = s_x2[p],     ya = s_y2[p],     za = s_z2[p],     sa = s_s2[p];
                u64 xb = s_x2[p + 1], yb = s_y2[p + 1], zb = s_z2[p + 1], sb = s_s2[p + 1];
#pragma unroll
                for (int k = 0; k < IPT; ++k) {
                    da[k] = ffma2(mz2[k], za, ffma2(my2[k], ya, ffma2(mx2[k], xa, sa)));
                    db[k] = ffma2(mz2[k], zb, ffma2(my2[k], yb, ffma2(mx2[k], xb, sb)));
                }
            }
            // half B distances (pairs p+2, p+3)
            u64 dc[IPT], dd[IPT];
            {
                u64 xc = s_x2[p + 2], yc = s_y2[p + 2], zc = s_z2[p + 2], sc = s_s2[p + 2];
                u64 xd = s_x2[p + 3], yd = s_y2[p + 3], zd = s_z2[p + 3], sd = s_s2[p + 3];
#pragma unroll
                for (int k = 0; k < IPT; ++k) {
                    dc[k] = ffma2(mz2[k], zc, ffma2(my2[k], yc, ffma2(mx2[k], xc, sc)));
                    dd[k] = ffma2(mz2[k], zd, ffma2(my2[k], yd, ffma2(mx2[k], xd, sd)));
                }
            }
#pragma unroll
            for (int k = 0; k < IPT; ++k) {
                float v0, v1, v2, v3, v4, v5, v6, v7;
                upk2(da[k], v0, v1);
                upk2(db[k], v2, v3);
                upk2(dc[k], v4, v5);
                upk2(dd[k], v6, v7);
                // half A (v0..v3): min + 2nd, save temps for lazy deep
                float t1a = fminf(v0, v1), t2a = fmaxf(v0, v1);
                float t3a = fminf(v2, v3), t4a = fmaxf(v2, v3);
                float s0a = fminf(t1a, t3a), m1a = fmaxf(t1a, t3a);
                float m2a = fminf(t2a, t4a);
                float s1a = fminf(m1a, m2a);
                // half B (v4..v7)
                float t1b = fminf(v4, v5), t2b = fmaxf(v4, v5);
                float t3b = fminf(v6, v7), t4b = fmaxf(v6, v7);
                float s0b = fminf(t1b, t3b), m1b = fmaxf(t1b, t3b);
                float m2b = fminf(t2b, t4b);
                float s1b = fminf(m1b, m2b);
                // group min: unconditional insert (no-op if not qualifying)
                float g0 = fminf(s0a, s0b);
                insert6(h[k], g0);
                // exact lower bound on ALL remaining 7 values of the group
                float loser = fmaxf(s0a, s0b);
                float cand = fminf(loser, fminf(s1a, s1b));
                bool c1 = cand < h[k][5];
                if (__any_sync(full, c1)) {
                    if (c1) {
                        heap_insert(h[k], loser);
                        heap_insert(h[k], s1a);
                        heap_insert(h[k], s1b);
                    }
                    // lazy deep values; gate is exact lower bound on them
                    float s2a = fmaxf(m1a, m2a), s2b = fmaxf(m1b, m2b);
                    bool c2 = fminf(s2a, s2b) < h[k][5];
                    if (__any_sync(full, c2)) {
                        if (c2) {
                            heap_insert(h[k], s2a);
                            heap_insert(h[k], s2b);
                            heap_insert(h[k], fmaxf(t2a, t4a));   // s3a
                            heap_insert(h[k], fmaxf(t2b, t4b));   // s3b
                        }
                    }
                }
            }
        }
    }

    // Fold packed chamfer halves
    float cmin[IPT];
#pragma unroll
    for (int k = 0; k < IPT; ++k) cmin[k] = fminf(cl[k], ch[k]);

    // ---- Cross-warp merge (3-round tree), reusing tile smem as buffer ----
    float* buf = sm;

#define MERGE_WRITE(SLOT)                                                   \
    {                                                                       \
        float* w = buf + (((size_t)(SLOT) * 32 + l) * IPT) * 7;             \
        _Pragma("unroll")                                                   \
        for (int k = 0; k < IPT; ++k) {                                     \
            w[k * 7 + 0] = cmin[k];                                         \
            _Pragma("unroll")                                               \
            for (int m = 0; m < 6; ++m) w[k * 7 + 1 + m] = h[k][m];         \
        }                                                                   \
    }
#define MERGE_READ(SLOT)                                                    \
    {                                                                       \
        const float* r = buf + (((size_t)(SLOT) * 32 + l) * IPT) * 7;       \
        _Pragma("unroll")                                                   \
        for (int k = 0; k < IPT; ++k) {                                     \
            cmin[k] = fminf(cmin[k], r[k * 7 + 0]);                         \
            _Pragma("unroll")                                               \
            for (int m = 0; m < 6; ++m) heap_insert(h[k], r[k * 7 + 1 + m]);\
        }                                                                   \
    }

    __syncthreads();
    if (seg >= 4) MERGE_WRITE(seg - 4);
    __syncthreads();
    if (seg < 4) MERGE_READ(seg);
    __syncthreads();
    if (seg == 2 || seg == 3) MERGE_WRITE(seg - 2);
    __syncthreads();
    if (seg < 2) MERGE_READ(seg);
    __syncthreads();
    if (seg == 1) MERGE_WRITE(0);
    __syncthreads();
    if (seg == 0) {
        MERGE_READ(0);
#pragma unroll
        for (int k = 0; k < IPT; ++k) {
            int i = ibase + l + 32 * k;
            g_cham[b * KP + i] = cmin[k] + ci[k];
            // drop h[0] (self), mean of next 5, re-add ci offset
            g_value[b * KP + i] =
                fmaf(0.2f, h[k][1] + h[k][2] + h[k][3] + h[k][4] + h[k][5], ci[k]);
        }
    }
}

// Warp-shuffle block reduction (256 thr): result valid in thread 0.
__device__ __forceinline__ float block_sum(float v, float* red) {
    const unsigned full = 0xffffffffu;
#pragma unroll
    for (int o = 16; o > 0; o >>= 1) v += __shfl_xor_sync(full, v, o);
    const int w = threadIdx.x >> 5;
    if ((threadIdx.x & 31) == 0) red[w] = v;
    __syncthreads();
    float r = 0.0f;
    if (threadIdx.x < 8) r = red[threadIdx.x];
#pragma unroll
    for (int o = 4; o > 0; o >>= 1) r += __shfl_xor_sync(full, r, o);
    __syncthreads();
    return r;   // thread 0 holds the sum
}

__global__ void __launch_bounds__(256)
reduce_kernel() {
    __shared__ float red[8];
    __shared__ float s_bcast[2];
    const int b = blockIdx.x;
    const int tid = threadIdx.x;
    const float* cham = g_cham + b * KP;
    const float* val  = g_value + b * KP;

    float s1 = 0.0f, s2 = 0.0f;
    for (int i = tid; i < KP; i += 256) { s1 += cham[i]; s2 += val[i]; }
    float cham_sum = block_sum(s1, red);
    float val_sum  = block_sum(s2, red);
    if (tid == 0) s_bcast[0] = val_sum * (1.0f / KP);
    __syncthreads();
    float mean = s_bcast[0];

    float s3 = 0.0f;
    for (int i = tid; i < KP; i += 256) {
        float d = val[i] - mean;
        s3 = fmaf(d, d, s3);
    }
    float var_sum = block_sum(s3, red);
    if (tid == 0) {
        float stdv = sqrtf(var_sum * (1.0f / (KP - 1)));   // ddof=1
        s_bcast[1] = fmaf(ALPHA, stdv, mean);
    }
    __syncthreads();
    float thr = s_bcast[1];

    float s4 = 0.0f;
    for (int i = tid; i < KP; i += 256) {
        float v = val[i];
        if (v > thr) s4 += v;
    }
    float msum = block_sum(s4, red);

    if (tid == 0) {
        float cham_mean = cham_sum * (1.0f / KP);
        float knn_mean  = msum * (1.0f / KP);
        g_batch[b] = cham_mean * W_CHAMFER + knn_mean * W_KNN;
    }
}

__global__ void final_kernel(float* __restrict__ out) {
    if (threadIdx.x == 0) {
        float s = 0.0f;
#pragma unroll
        for (int b = 0; b < BP; ++b) s += g_batch[b];
        out[0] = s * (1.0f / BP);
    }
}

extern "C" void kernel_launch(void* const* d_in, const int* in_sizes, int n_in,
                              void* d_out, int out_size) {
    const float* adv = (const float*)d_in[0];
    const float* ori = (const float*)d_in[1];
    float* out = (float*)d_out;

    dist_kernel<<<dim3(KP / TILE_I, BP), THREADS, SMEM_BYTES>>>(adv, ori);
    reduce_kernel<<<BP, 256>>>();
    final_kernel<<<1, 32>>>(out);
}